// round 13
// baseline (speedup 1.0000x reference)
#include <cuda_runtime.h>
#include <cuda_fp16.h>
#include <cstdint>

#define NNODES 4096
#define RREL   16
#define NBASES 8
#define DIN    64
#define DOUT   32
#define KFULL  (RREL * NNODES)          // 65536

#define M_TILE 128
#define KT     64                       // k per step (4 mma k-tiles of 16)
#define KSPLIT 64
#define KCHUNK (KFULL / KSPLIT)         // 1024
#define NSTEPS (KCHUNK / KT)            // 16

// gemm smem: A f16 tiles 2 x 16KB | B 4-slot ring, each slot BH 4K + BL 4K
#define OFF_B  32768
#define B_STG  8192
#define SMEM_BYTES (32768 + 4 * B_STG)  // 64 KB dynamic

#define XP 68                           // k_fw X smem pitch (floats)
#define FW_ROWS 64                      // k_fw tile rows

__device__ __half g_Bh[(size_t)DOUT * KFULL];            // [c][k], 4 MB
__device__ __half g_Bl[(size_t)DOUT * KFULL];            // 4 MB
__device__ __half g_part[(size_t)KSPLIT * NNODES * DOUT]; // fp16 partials, 16 MB

__device__ __forceinline__ void mma16816(float* d, const uint32_t* a,
                                         uint32_t b0, uint32_t b1) {
    asm volatile(
        "mma.sync.aligned.m16n8k16.row.col.f32.f16.f16.f32 "
        "{%0,%1,%2,%3}, {%4,%5,%6,%7}, {%8,%9}, {%0,%1,%2,%3};"
        : "+f"(d[0]), "+f"(d[1]), "+f"(d[2]), "+f"(d[3])
        : "r"(a[0]), "r"(a[1]), "r"(a[2]), "r"(a[3]), "r"(b0), "r"(b1));
}
__device__ __forceinline__ void cp_async16(uint32_t saddr, const void* g) {
    asm volatile("cp.async.cg.shared.global [%0], [%1], 16;" :: "r"(saddr), "l"(g));
}
__device__ __forceinline__ void ldmatrix_x4(uint32_t* r, uint32_t addr) {
    asm volatile("ldmatrix.sync.aligned.m8n8.x4.shared.b16 {%0,%1,%2,%3}, [%4];"
                 : "=r"(r[0]), "=r"(r[1]), "=r"(r[2]), "=r"(r[3]) : "r"(addr));
}
// evict-first streaming load (A is single-use; keep B hot in L2)
__device__ __forceinline__ float4 ldcs4(const float* p) {
    float4 v;
    asm volatile("ld.global.cs.v4.f32 {%0,%1,%2,%3}, [%4];"
                 : "=f"(v.x), "=f"(v.y), "=f"(v.z), "=f"(v.w) : "l"(p));
    return v;
}

// Stage 1+2: W_r = comp[r] . WF, FW = X @ W_r -> fp16 hi/lo, transposed [c][k].
// 64-row tiles (grid 1024) for occupancy/latency; 2x4 register block per thread.
__global__ __launch_bounds__(256) void k_fw(const float* __restrict__ X,
                                            const float* __restrict__ WF,
                                            const float* __restrict__ comp) {
    __shared__ float Ws[DIN * DOUT];        // 8 KB
    __shared__ float Xs[FW_ROWS * XP];      // 17.4 KB
    const int r = blockIdx.x, nblk = blockIdx.y, t = threadIdx.x;

    // W_r: 2048 entries, 8 per thread
#pragma unroll
    for (int j = 0; j < 8; ++j) {
        int ij = t + 256 * j;
        float s = 0.f;
#pragma unroll
        for (int b = 0; b < NBASES; ++b)
            s += comp[r * NBASES + b] * WF[b * (DIN * DOUT) + ij];
        Ws[ij] = s;
    }
    // X tile: 64 rows x 64, coalesced float4 loads (4 per thread)
#pragma unroll
    for (int i = 0; i < 4; ++i) {
        int idx = t + 256 * i;              // 0..1023
        int row = idx >> 4, c4 = idx & 15;
        float4 v = *(const float4*)&X[(size_t)(nblk * FW_ROWS + row) * DIN + c4 * 4];
        *(float4*)&Xs[row * XP + c4 * 4] = v;
    }
    __syncthreads();

    const int rg = t >> 3;              // rows rg + 32*i, i in 0..1
    const int cg = (t & 7) * 4;         // cols cg..cg+3
    float acc[2][4] = {};

#pragma unroll
    for (int k = 0; k < DIN; k += 4) {
        float4 w0 = *(const float4*)&Ws[(k + 0) * DOUT + cg];
        float4 w1 = *(const float4*)&Ws[(k + 1) * DOUT + cg];
        float4 w2 = *(const float4*)&Ws[(k + 2) * DOUT + cg];
        float4 w3 = *(const float4*)&Ws[(k + 3) * DOUT + cg];
#pragma unroll
        for (int i = 0; i < 2; ++i) {
            float4 x = *(const float4*)&Xs[(rg + 32 * i) * XP + k];
            acc[i][0] += x.x * w0.x + x.y * w1.x + x.z * w2.x + x.w * w3.x;
            acc[i][1] += x.x * w0.y + x.y * w1.y + x.z * w2.y + x.w * w3.y;
            acc[i][2] += x.x * w0.z + x.y * w1.z + x.z * w2.z + x.w * w3.z;
            acc[i][3] += x.x * w0.w + x.y * w1.w + x.z * w2.w + x.w * w3.w;
        }
    }

    const int kbase = r * NNODES + nblk * FW_ROWS;
#pragma unroll
    for (int i = 0; i < 2; ++i)
#pragma unroll
        for (int j = 0; j < 4; ++j) {
            float v = acc[i][j];
            __half h = __float2half_rn(v);
            __half l = __float2half_rn(v - __half2float(h));
            size_t o = (size_t)(cg + j) * KFULL + kbase + rg + 32 * i;
            g_Bh[o] = h;
            g_Bl[o] = l;
        }
}

// Stage 3: split-K GEMM. Streaming LDG.cs -> in-reg fp16 convert -> swizzled
// smem (A 2-buf, B 4-slot cp.async ring) -> ldmatrix x4 -> 2-product mma.
__global__ __launch_bounds__(256, 2) void k_gemm(const float* __restrict__ A) {
    extern __shared__ char smem[];
    const uint32_t sbase = (uint32_t)__cvta_generic_to_shared(smem);

    const int t    = threadIdx.x;
    const int wid  = t >> 5, lane = t & 31;
    const int m0   = blockIdx.x * M_TILE;
    const size_t kb0 = (size_t)blockIdx.y * KCHUNK;

    const int wr = wid >> 1;
    const int wn = wid & 1;

    const int arow0 = t >> 4;
    const int apos  = t & 15;
    const float* Asrc = A + (size_t)m0 * KFULL + kb0 + apos * 4;

    const int bn = t >> 3, bkc = t & 7;
    const uint32_t boff = bn * 128 + ((bkc ^ (bn & 7)) << 4);
    const __half* bsrc_h = g_Bh + (size_t)bn * KFULL + kb0 + bkc * 8;
    const __half* bsrc_l = g_Bl + (size_t)bn * KFULL + kb0 + bkc * 8;

    const int a_row  = wr * 32 + (lane & 15);
    const int a_csel = lane >> 4;
    const int bg     = lane >> 3;
    const int b_nrow = wn * 16 + ((bg >> 1) << 3) + (lane & 7);
    const int b_csel = bg & 1;

    cp_async16(sbase + OFF_B + 0 * B_STG + boff, bsrc_h);
    cp_async16(sbase + OFF_B + 0 * B_STG + 4096 + boff, bsrc_l);
    asm volatile("cp.async.commit_group;");
    cp_async16(sbase + OFF_B + 1 * B_STG + boff, bsrc_h + KT);
    cp_async16(sbase + OFF_B + 1 * B_STG + 4096 + boff, bsrc_l + KT);
    asm volatile("cp.async.commit_group;");

    float4 areg[8];
#pragma unroll
    for (int i = 0; i < 8; ++i)
        areg[i] = ldcs4(Asrc + (size_t)(arow0 + 16 * i) * KFULL);

    float d[2][2][4] = {};

    for (int step = 0; step < NSTEPS; ++step) {
        const int abuf = step & 1;
        const uint32_t asm_base = sbase + abuf * 16384;

        {
            const int chunk = apos >> 1, half = apos & 1;
#pragma unroll
            for (int i = 0; i < 8; ++i) {
                const int row = arow0 + 16 * i;
                float4 f = areg[i];
                uint32_t h01, h23;
                asm("cvt.rn.f16x2.f32 %0, %1, %2;" : "=r"(h01) : "f"(f.y), "f"(f.x));
                asm("cvt.rn.f16x2.f32 %0, %1, %2;" : "=r"(h23) : "f"(f.w), "f"(f.z));
                const uint32_t off = row * 128 + ((chunk ^ (row & 7)) << 4) + half * 8;
                *(uint2*)(smem + abuf * 16384 + off) = make_uint2(h01, h23);
            }
        }

        if (step + 1 < NSTEPS) {
            const float* asrc2 = Asrc + (step + 1) * KT;
#pragma unroll
            for (int i = 0; i < 8; ++i)
                areg[i] = ldcs4(asrc2 + (size_t)(arow0 + 16 * i) * KFULL);
        }
        if (step + 2 < NSTEPS) {
            const uint32_t bslot = sbase + OFF_B + ((step + 2) & 3) * B_STG;
            cp_async16(bslot + boff, bsrc_h + (step + 2) * KT);
            cp_async16(bslot + 4096 + boff, bsrc_l + (step + 2) * KT);
        }
        asm volatile("cp.async.commit_group;");
        asm volatile("cp.async.wait_group 2;");
        __syncthreads();

        const uint32_t a_base0 = asm_base + a_row * 128;
        const uint32_t a_base1 = a_base0 + 16 * 128;
        const uint32_t bstg    = sbase + OFF_B + (step & 3) * B_STG + b_nrow * 128;
#pragma unroll
        for (int kt = 0; kt < 4; ++kt) {
            const int achunk = (2 * kt + a_csel) ^ (lane & 7);
            const int bchunk = (2 * kt + b_csel) ^ (lane & 7);
            uint32_t a0[4], a1[4], bh4[4], bl4[4];
            ldmatrix_x4(a0, a_base0 + (achunk << 4));
            ldmatrix_x4(a1, a_base1 + (achunk << 4));
            ldmatrix_x4(bh4, bstg + (bchunk << 4));
            ldmatrix_x4(bl4, bstg + 4096 + (bchunk << 4));
            mma16816(d[0][0], a0, bh4[0], bh4[1]);
            mma16816(d[0][0], a0, bl4[0], bl4[1]);
            mma16816(d[0][1], a0, bh4[2], bh4[3]);
            mma16816(d[0][1], a0, bl4[2], bl4[3]);
            mma16816(d[1][0], a1, bh4[0], bh4[1]);
            mma16816(d[1][0], a1, bl4[0], bl4[1]);
            mma16816(d[1][1], a1, bh4[2], bh4[3]);
            mma16816(d[1][1], a1, bl4[2], bl4[3]);
        }
    }

    // epilogue: fp16 partials
    const int r4 = lane >> 2, kq = (lane & 3) * 2;
    __half* po = g_part + ((size_t)blockIdx.y * NNODES + m0 + wr * 32 + r4) * DOUT
                        + wn * 16 + kq;
#pragma unroll
    for (int rt = 0; rt < 2; ++rt)
#pragma unroll
        for (int nn = 0; nn < 2; ++nn) {
            *(__half2*)(po + (size_t)(rt * 16)     * DOUT + nn * 8) =
                __floats2half2_rn(d[rt][nn][0], d[rt][nn][1]);
            *(__half2*)(po + (size_t)(rt * 16 + 8) * DOUT + nn * 8) =
                __floats2half2_rn(d[rt][nn][2], d[rt][nn][3]);
        }
}

// Stage 4: deterministic split-K reduction, uint4 (8-half) granularity
__global__ void k_reduce(float* __restrict__ out) {
    int i = blockIdx.x * blockDim.x + threadIdx.x;   // over 16384 uint4s
    const uint4* p = (const uint4*)g_part;
    float s[8] = {};
#pragma unroll
    for (int sdx = 0; sdx < KSPLIT; ++sdx) {
        uint4 v = p[(size_t)sdx * (NNODES * DOUT / 8) + i];
        float2 f0 = __half22float2(*(__half2*)&v.x);
        float2 f1 = __half22float2(*(__half2*)&v.y);
        float2 f2 = __half22float2(*(__half2*)&v.z);
        float2 f3 = __half22float2(*(__half2*)&v.w);
        s[0] += f0.x; s[1] += f0.y; s[2] += f1.x; s[3] += f1.y;
        s[4] += f2.x; s[5] += f2.y; s[6] += f3.x; s[7] += f3.y;
    }
    float4* o = (float4*)(out + (size_t)i * 8);
    o[0] = make_float4(s[0], s[1], s[2], s[3]);
    o[1] = make_float4(s[4], s[5], s[6], s[7]);
}

extern "C" void kernel_launch(void* const* d_in, const int* in_sizes, int n_in,
                              void* d_out, int out_size) {
    const float* X    = (const float*)d_in[0];   // [4096, 64]
    const float* A    = (const float*)d_in[1];   // [4096, 65536]
    const float* WF   = (const float*)d_in[2];   // [8, 64, 32]
    const float* comp = (const float*)d_in[3];   // [16, 8]
    float* out = (float*)d_out;                  // [4096, 32]

    cudaFuncSetAttribute((const void*)k_gemm,
                         cudaFuncAttributeMaxDynamicSharedMemorySize, SMEM_BYTES);

    k_fw<<<dim3(RREL, NNODES / FW_ROWS), 256>>>(X, WF, comp);
    k_gemm<<<dim3(NNODES / M_TILE, KSPLIT), 256, SMEM_BYTES>>>(A);
    k_reduce<<<(NNODES * DOUT / 8) / 256, 256>>>(out);
}

// round 14
// speedup vs baseline: 1.0338x; 1.0338x over previous
#include <cuda_runtime.h>
#include <cuda_fp16.h>
#include <cstdint>

#define NNODES 4096
#define RREL   16
#define NBASES 8
#define DIN    64
#define DOUT   32
#define KFULL  (RREL * NNODES)          // 65536

#define M_TILE 128
#define KT     64                       // k per step (4 mma k-tiles of 16)
#define KSPLIT 64
#define KCHUNK (KFULL / KSPLIT)         // 1024
#define NSTEPS (KCHUNK / KT)            // 16

// gemm smem: A f16 tiles 2 x 16KB | B 4-slot ring, each slot BH 4K + BL 4K
#define OFF_B  32768
#define B_STG  8192
#define SMEM_BYTES (32768 + 4 * B_STG)  // 64 KB dynamic

#define XP 68                           // k_fw X smem pitch (floats)
#define SP 68                           // k_fw staging pitch (halves)
#define FW_ROWS 64                      // k_fw tile rows

__device__ __half g_Bh[(size_t)DOUT * KFULL];            // [c][k], 4 MB
__device__ __half g_Bl[(size_t)DOUT * KFULL];            // 4 MB
__device__ __half g_part[(size_t)KSPLIT * NNODES * DOUT]; // fp16 partials, 16 MB

__device__ __forceinline__ void mma16816(float* d, const uint32_t* a,
                                         uint32_t b0, uint32_t b1) {
    asm volatile(
        "mma.sync.aligned.m16n8k16.row.col.f32.f16.f16.f32 "
        "{%0,%1,%2,%3}, {%4,%5,%6,%7}, {%8,%9}, {%0,%1,%2,%3};"
        : "+f"(d[0]), "+f"(d[1]), "+f"(d[2]), "+f"(d[3])
        : "r"(a[0]), "r"(a[1]), "r"(a[2]), "r"(a[3]), "r"(b0), "r"(b1));
}
__device__ __forceinline__ void cp_async16(uint32_t saddr, const void* g) {
    asm volatile("cp.async.cg.shared.global [%0], [%1], 16;" :: "r"(saddr), "l"(g));
}
__device__ __forceinline__ void ldmatrix_x4(uint32_t* r, uint32_t addr) {
    asm volatile("ldmatrix.sync.aligned.m8n8.x4.shared.b16 {%0,%1,%2,%3}, [%4];"
                 : "=r"(r[0]), "=r"(r[1]), "=r"(r[2]), "=r"(r[3]) : "r"(addr));
}
// evict-first streaming load (A is single-use; keep B hot in L2)
__device__ __forceinline__ float4 ldcs4(const float* p) {
    float4 v;
    asm volatile("ld.global.cs.v4.f32 {%0,%1,%2,%3}, [%4];"
                 : "=f"(v.x), "=f"(v.y), "=f"(v.z), "=f"(v.w) : "l"(p));
    return v;
}

// Stage 1+2: W_r = comp[r] . WF, FW = X @ W_r -> fp16 hi/lo, transposed [c][k].
// 2x4 register block per thread (adjacent k rows), smem-transposed epilogue
// so all global stores are contiguous 128B-per-column streams.
__global__ __launch_bounds__(256) void k_fw(const float* __restrict__ X,
                                            const float* __restrict__ WF,
                                            const float* __restrict__ comp) {
    __shared__ float Ws[DIN * DOUT];        // 8 KB
    __shared__ float Xs[FW_ROWS * XP];      // 17.4 KB
    __shared__ __half Sh[DOUT * SP];        // 4.4 KB staging (hi)
    __shared__ __half Sl[DOUT * SP];        // 4.4 KB staging (lo)
    const int r = blockIdx.x, nblk = blockIdx.y, t = threadIdx.x;

    // W_r: 2048 entries, 8 per thread
#pragma unroll
    for (int j = 0; j < 8; ++j) {
        int ij = t + 256 * j;
        float s = 0.f;
#pragma unroll
        for (int b = 0; b < NBASES; ++b)
            s += comp[r * NBASES + b] * WF[b * (DIN * DOUT) + ij];
        Ws[ij] = s;
    }
    // X tile: 64 rows x 64, coalesced float4 loads (4 per thread)
#pragma unroll
    for (int i = 0; i < 4; ++i) {
        int idx = t + 256 * i;              // 0..1023
        int row = idx >> 4, c4 = idx & 15;
        float4 v = *(const float4*)&X[(size_t)(nblk * FW_ROWS + row) * DIN + c4 * 4];
        *(float4*)&Xs[row * XP + c4 * 4] = v;
    }
    __syncthreads();

    const int rg = t >> 3;              // rows 2rg, 2rg+1
    const int cg = (t & 7) * 4;         // cols cg..cg+3
    float acc[2][4] = {};

#pragma unroll
    for (int k = 0; k < DIN; k += 4) {
        float4 w0 = *(const float4*)&Ws[(k + 0) * DOUT + cg];
        float4 w1 = *(const float4*)&Ws[(k + 1) * DOUT + cg];
        float4 w2 = *(const float4*)&Ws[(k + 2) * DOUT + cg];
        float4 w3 = *(const float4*)&Ws[(k + 3) * DOUT + cg];
#pragma unroll
        for (int i = 0; i < 2; ++i) {
            float4 x = *(const float4*)&Xs[(2 * rg + i) * XP + k];
            acc[i][0] += x.x * w0.x + x.y * w1.x + x.z * w2.x + x.w * w3.x;
            acc[i][1] += x.x * w0.y + x.y * w1.y + x.z * w2.y + x.w * w3.y;
            acc[i][2] += x.x * w0.z + x.y * w1.z + x.z * w2.z + x.w * w3.z;
            acc[i][3] += x.x * w0.w + x.y * w1.w + x.z * w2.w + x.w * w3.w;
        }
    }

    // stage hi/lo into transposed smem tiles (half2 per column, adjacent k)
#pragma unroll
    for (int j = 0; j < 4; ++j) {
        float v0 = acc[0][j], v1 = acc[1][j];
        __half h0 = __float2half_rn(v0), h1 = __float2half_rn(v1);
        __half l0 = __float2half_rn(v0 - __half2float(h0));
        __half l1 = __float2half_rn(v1 - __half2float(h1));
        *(__half2*)&Sh[(cg + j) * SP + 2 * rg] = __halves2half2(h0, h1);
        *(__half2*)&Sl[(cg + j) * SP + 2 * rg] = __halves2half2(l0, l1);
    }
    __syncthreads();

    // coalesced writeout: per column 64 contiguous halves (128 B)
    const int kbase = r * NNODES + nblk * FW_ROWS;
#pragma unroll
    for (int q = 0; q < 2; ++q) {
        int idx = t + 256 * q;              // 0..511
        int col = idx >> 4, ch = idx & 15;  // 16 uint2 chunks of 4 halves
        uint2 vh = *(const uint2*)&Sh[col * SP + ch * 4];
        uint2 vl = *(const uint2*)&Sl[col * SP + ch * 4];
        *(uint2*)&g_Bh[(size_t)col * KFULL + kbase + ch * 4] = vh;
        *(uint2*)&g_Bl[(size_t)col * KFULL + kbase + ch * 4] = vl;
    }
}

// Stage 3: split-K GEMM. Streaming LDG.cs -> in-reg fp16 convert -> swizzled
// smem (A 2-buf, B 4-slot cp.async ring) -> ldmatrix x4 -> 2-product mma.
__global__ __launch_bounds__(256, 2) void k_gemm(const float* __restrict__ A) {
    extern __shared__ char smem[];
    const uint32_t sbase = (uint32_t)__cvta_generic_to_shared(smem);

    const int t    = threadIdx.x;
    const int wid  = t >> 5, lane = t & 31;
    const int m0   = blockIdx.x * M_TILE;
    const size_t kb0 = (size_t)blockIdx.y * KCHUNK;

    const int wr = wid >> 1;
    const int wn = wid & 1;

    const int arow0 = t >> 4;
    const int apos  = t & 15;
    const float* Asrc = A + (size_t)m0 * KFULL + kb0 + apos * 4;

    const int bn = t >> 3, bkc = t & 7;
    const uint32_t boff = bn * 128 + ((bkc ^ (bn & 7)) << 4);
    const __half* bsrc_h = g_Bh + (size_t)bn * KFULL + kb0 + bkc * 8;
    const __half* bsrc_l = g_Bl + (size_t)bn * KFULL + kb0 + bkc * 8;

    const int a_row  = wr * 32 + (lane & 15);
    const int a_csel = lane >> 4;
    const int bg     = lane >> 3;
    const int b_nrow = wn * 16 + ((bg >> 1) << 3) + (lane & 7);
    const int b_csel = bg & 1;

    cp_async16(sbase + OFF_B + 0 * B_STG + boff, bsrc_h);
    cp_async16(sbase + OFF_B + 0 * B_STG + 4096 + boff, bsrc_l);
    asm volatile("cp.async.commit_group;");
    cp_async16(sbase + OFF_B + 1 * B_STG + boff, bsrc_h + KT);
    cp_async16(sbase + OFF_B + 1 * B_STG + 4096 + boff, bsrc_l + KT);
    asm volatile("cp.async.commit_group;");

    float4 areg[8];
#pragma unroll
    for (int i = 0; i < 8; ++i)
        areg[i] = ldcs4(Asrc + (size_t)(arow0 + 16 * i) * KFULL);

    float d[2][2][4] = {};

    for (int step = 0; step < NSTEPS; ++step) {
        const int abuf = step & 1;
        const uint32_t asm_base = sbase + abuf * 16384;

        {
            const int chunk = apos >> 1, half = apos & 1;
#pragma unroll
            for (int i = 0; i < 8; ++i) {
                const int row = arow0 + 16 * i;
                float4 f = areg[i];
                uint32_t h01, h23;
                asm("cvt.rn.f16x2.f32 %0, %1, %2;" : "=r"(h01) : "f"(f.y), "f"(f.x));
                asm("cvt.rn.f16x2.f32 %0, %1, %2;" : "=r"(h23) : "f"(f.w), "f"(f.z));
                const uint32_t off = row * 128 + ((chunk ^ (row & 7)) << 4) + half * 8;
                *(uint2*)(smem + abuf * 16384 + off) = make_uint2(h01, h23);
            }
        }

        if (step + 1 < NSTEPS) {
            const float* asrc2 = Asrc + (step + 1) * KT;
#pragma unroll
            for (int i = 0; i < 8; ++i)
                areg[i] = ldcs4(asrc2 + (size_t)(arow0 + 16 * i) * KFULL);
        }
        if (step + 2 < NSTEPS) {
            const uint32_t bslot = sbase + OFF_B + ((step + 2) & 3) * B_STG;
            cp_async16(bslot + boff, bsrc_h + (step + 2) * KT);
            cp_async16(bslot + 4096 + boff, bsrc_l + (step + 2) * KT);
        }
        asm volatile("cp.async.commit_group;");
        asm volatile("cp.async.wait_group 2;");
        __syncthreads();

        const uint32_t a_base0 = asm_base + a_row * 128;
        const uint32_t a_base1 = a_base0 + 16 * 128;
        const uint32_t bstg    = sbase + OFF_B + (step & 3) * B_STG + b_nrow * 128;
#pragma unroll
        for (int kt = 0; kt < 4; ++kt) {
            const int achunk = (2 * kt + a_csel) ^ (lane & 7);
            const int bchunk = (2 * kt + b_csel) ^ (lane & 7);
            uint32_t a0[4], a1[4], bh4[4], bl4[4];
            ldmatrix_x4(a0, a_base0 + (achunk << 4));
            ldmatrix_x4(a1, a_base1 + (achunk << 4));
            ldmatrix_x4(bh4, bstg + (bchunk << 4));
            ldmatrix_x4(bl4, bstg + 4096 + (bchunk << 4));
            mma16816(d[0][0], a0, bh4[0], bh4[1]);
            mma16816(d[0][0], a0, bl4[0], bl4[1]);
            mma16816(d[0][1], a0, bh4[2], bh4[3]);
            mma16816(d[0][1], a0, bl4[2], bl4[3]);
            mma16816(d[1][0], a1, bh4[0], bh4[1]);
            mma16816(d[1][0], a1, bl4[0], bl4[1]);
            mma16816(d[1][1], a1, bh4[2], bh4[3]);
            mma16816(d[1][1], a1, bl4[2], bl4[3]);
        }
    }

    // epilogue: fp16 partials
    const int r4 = lane >> 2, kq = (lane & 3) * 2;
    __half* po = g_part + ((size_t)blockIdx.y * NNODES + m0 + wr * 32 + r4) * DOUT
                        + wn * 16 + kq;
#pragma unroll
    for (int rt = 0; rt < 2; ++rt)
#pragma unroll
        for (int nn = 0; nn < 2; ++nn) {
            *(__half2*)(po + (size_t)(rt * 16)     * DOUT + nn * 8) =
                __floats2half2_rn(d[rt][nn][0], d[rt][nn][1]);
            *(__half2*)(po + (size_t)(rt * 16 + 8) * DOUT + nn * 8) =
                __floats2half2_rn(d[rt][nn][2], d[rt][nn][3]);
        }
}

// Stage 4: deterministic split-K reduction (half2 grain, 4 split streams for MLP)
__global__ void k_reduce(float* __restrict__ out) {
    int i = blockIdx.x * blockDim.x + threadIdx.x;   // over 65536 half2s
    const __half2* p = (const __half2*)g_part;
    const size_t stride = (size_t)(NNODES * DOUT / 2);
    float2 s0 = {0.f, 0.f}, s1 = {0.f, 0.f}, s2 = {0.f, 0.f}, s3 = {0.f, 0.f};
#pragma unroll
    for (int sdx = 0; sdx < KSPLIT; sdx += 4) {
        float2 v0 = __half22float2(p[(size_t)(sdx + 0) * stride + i]);
        float2 v1 = __half22float2(p[(size_t)(sdx + 1) * stride + i]);
        float2 v2 = __half22float2(p[(size_t)(sdx + 2) * stride + i]);
        float2 v3 = __half22float2(p[(size_t)(sdx + 3) * stride + i]);
        s0.x += v0.x; s0.y += v0.y; s1.x += v1.x; s1.y += v1.y;
        s2.x += v2.x; s2.y += v2.y; s3.x += v3.x; s3.y += v3.y;
    }
    float2 s = make_float2(s0.x + s1.x + s2.x + s3.x,
                           s0.y + s1.y + s2.y + s3.y);
    ((float2*)out)[i] = s;
}

extern "C" void kernel_launch(void* const* d_in, const int* in_sizes, int n_in,
                              void* d_out, int out_size) {
    const float* X    = (const float*)d_in[0];   // [4096, 64]
    const float* A    = (const float*)d_in[1];   // [4096, 65536]
    const float* WF   = (const float*)d_in[2];   // [8, 64, 32]
    const float* comp = (const float*)d_in[3];   // [16, 8]
    float* out = (float*)d_out;                  // [4096, 32]

    cudaFuncSetAttribute((const void*)k_gemm,
                         cudaFuncAttributeMaxDynamicSharedMemorySize, SMEM_BYTES);

    k_fw<<<dim3(RREL, NNODES / FW_ROWS), 256>>>(X, WF, comp);
    k_gemm<<<dim3(NNODES / M_TILE, KSPLIT), 256, SMEM_BYTES>>>(A);
    k_reduce<<<(NNODES * DOUT / 2) / 256, 256>>>(out);
}

// round 16
// speedup vs baseline: 1.0447x; 1.0105x over previous
#include <cuda_runtime.h>
#include <cuda_fp16.h>
#include <cstdint>

#define NNODES 4096
#define RREL   16
#define NBASES 8
#define DIN    64
#define DOUT   32
#define KFULL  (RREL * NNODES)          // 65536

#define M_TILE 128
#define KT     64                       // k per step (4 mma k-tiles of 16)
#define KSPLIT 64
#define KCHUNK (KFULL / KSPLIT)         // 1024
#define NSTEPS (KCHUNK / KT)            // 16

// gemm smem: A f16 tiles 2 x 16KB | B 4-slot ring, each slot BH 4K + BL 4K
#define OFF_B  32768
#define B_STG  8192
#define SMEM_BYTES (32768 + 4 * B_STG)  // 64 KB dynamic

#define XP 68                           // k_fw X smem pitch (floats)
#define SP2 136                         // k_fw staging pitch (halves, 16B-mult)
#define FW_ROWS 128                     // k_fw tile rows

__device__ __half g_Bh[(size_t)DOUT * KFULL];            // [c][k], 4 MB
__device__ __half g_Bl[(size_t)DOUT * KFULL];            // 4 MB
__device__ __half g_part[(size_t)KSPLIT * NNODES * DOUT]; // fp16 partials, 16 MB

__device__ __forceinline__ void mma16816(float* d, const uint32_t* a,
                                         uint32_t b0, uint32_t b1) {
    asm volatile(
        "mma.sync.aligned.m16n8k16.row.col.f32.f16.f16.f32 "
        "{%0,%1,%2,%3}, {%4,%5,%6,%7}, {%8,%9}, {%0,%1,%2,%3};"
        : "+f"(d[0]), "+f"(d[1]), "+f"(d[2]), "+f"(d[3])
        : "r"(a[0]), "r"(a[1]), "r"(a[2]), "r"(a[3]), "r"(b0), "r"(b1));
}
__device__ __forceinline__ void cp_async16(uint32_t saddr, const void* g) {
    asm volatile("cp.async.cg.shared.global [%0], [%1], 16;" :: "r"(saddr), "l"(g));
}
__device__ __forceinline__ void ldmatrix_x4(uint32_t* r, uint32_t addr) {
    asm volatile("ldmatrix.sync.aligned.m8n8.x4.shared.b16 {%0,%1,%2,%3}, [%4];"
                 : "=r"(r[0]), "=r"(r[1]), "=r"(r[2]), "=r"(r[3]) : "r"(addr));
}
// evict-first streaming load (A is single-use; keep B hot in L2)
__device__ __forceinline__ float4 ldcs4(const float* p) {
    float4 v;
    asm volatile("ld.global.cs.v4.f32 {%0,%1,%2,%3}, [%4];"
                 : "=f"(v.x), "=f"(v.y), "=f"(v.z), "=f"(v.w) : "l"(p));
    return v;
}

// Stage 1+2: W_r = comp[r] . WF, FW = X @ W_r -> fp16 hi/lo, transposed [c][k].
// 4x4 register block per thread (rows 4rg..4rg+3), staging tiles overlay Xs,
// coalesced 256B-per-column global writeout (2 uint4 iterations per thread).
__global__ __launch_bounds__(256) void k_fw(const float* __restrict__ X,
                                            const float* __restrict__ WF,
                                            const float* __restrict__ comp) {
    __shared__ __align__(16) char fwsm[8192 + FW_ROWS * XP * 4];   // 43 KB
    float* Ws = (float*)fwsm;                       // 8 KB
    float* Xs = (float*)(fwsm + 8192);              // 34.8 KB
    __half* Sh = (__half*)(fwsm + 8192);            // staging hi (overlays Xs)
    __half* Sl = (__half*)(fwsm + 8192 + DOUT * SP2 * 2);  // staging lo

    const int r = blockIdx.x, nblk = blockIdx.y, t = threadIdx.x;

    // W_r: 2048 entries, 8 per thread
#pragma unroll
    for (int j = 0; j < 8; ++j) {
        int ij = t + 256 * j;
        float s = 0.f;
#pragma unroll
        for (int b = 0; b < NBASES; ++b)
            s += comp[r * NBASES + b] * WF[b * (DIN * DOUT) + ij];
        Ws[ij] = s;
    }
    // X tile: 128 rows x 64, coalesced float4 loads (8 per thread)
#pragma unroll
    for (int i = 0; i < 8; ++i) {
        int idx = t + 256 * i;              // 0..2047
        int row = idx >> 4, c4 = idx & 15;
        float4 v = *(const float4*)&X[(size_t)(nblk * FW_ROWS + row) * DIN + c4 * 4];
        *(float4*)&Xs[row * XP + c4 * 4] = v;
    }
    __syncthreads();

    const int rg = t >> 3;              // rows 4rg .. 4rg+3
    const int cg = (t & 7) * 4;         // cols cg..cg+3
    float acc[4][4] = {};

#pragma unroll
    for (int k = 0; k < DIN; k += 4) {
        float4 w0 = *(const float4*)&Ws[(k + 0) * DOUT + cg];
        float4 w1 = *(const float4*)&Ws[(k + 1) * DOUT + cg];
        float4 w2 = *(const float4*)&Ws[(k + 2) * DOUT + cg];
        float4 w3 = *(const float4*)&Ws[(k + 3) * DOUT + cg];
#pragma unroll
        for (int i = 0; i < 4; ++i) {
            float4 x = *(const float4*)&Xs[(4 * rg + i) * XP + k];
            acc[i][0] += x.x * w0.x + x.y * w1.x + x.z * w2.x + x.w * w3.x;
            acc[i][1] += x.x * w0.y + x.y * w1.y + x.z * w2.y + x.w * w3.y;
            acc[i][2] += x.x * w0.z + x.y * w1.z + x.z * w2.z + x.w * w3.z;
            acc[i][3] += x.x * w0.w + x.y * w1.w + x.z * w2.w + x.w * w3.w;
        }
    }
    __syncthreads();    // Xs reads done before staging overlays it

    // stage hi/lo into transposed smem tiles (uint2 = 4 adjacent k per column)
#pragma unroll
    for (int j = 0; j < 4; ++j) {
        __half h[4], l[4];
#pragma unroll
        for (int i = 0; i < 4; ++i) {
            float v = acc[i][j];
            h[i] = __float2half_rn(v);
            l[i] = __float2half_rn(v - __half2float(h[i]));
        }
        int so = (cg + j) * SP2 + 4 * rg;
        *(__half2*)&Sh[so]     = __halves2half2(h[0], h[1]);
        *(__half2*)&Sh[so + 2] = __halves2half2(h[2], h[3]);
        *(__half2*)&Sl[so]     = __halves2half2(l[0], l[1]);
        *(__half2*)&Sl[so + 2] = __halves2half2(l[2], l[3]);
    }
    __syncthreads();

    // coalesced writeout: 32 cols x 16 uint4 chunks = full 128-row tile
    const int kbase = r * NNODES + nblk * FW_ROWS;
#pragma unroll
    for (int q = 0; q < 2; ++q) {
        int idx = t + 256 * q;              // 0..511
        int col = idx >> 4, ch = idx & 15;
        uint4 vh = *(const uint4*)&Sh[col * SP2 + ch * 8];
        uint4 vl = *(const uint4*)&Sl[col * SP2 + ch * 8];
        *(uint4*)&g_Bh[(size_t)col * KFULL + kbase + ch * 8] = vh;
        *(uint4*)&g_Bl[(size_t)col * KFULL + kbase + ch * 8] = vl;
    }
}

// Stage 3: split-K GEMM. Streaming LDG.cs -> in-reg fp16 convert -> swizzled
// smem (A 2-buf, B 4-slot cp.async ring) -> ldmatrix x4 -> 2-product mma.
__global__ __launch_bounds__(256, 2) void k_gemm(const float* __restrict__ A) {
    extern __shared__ char smem[];
    const uint32_t sbase = (uint32_t)__cvta_generic_to_shared(smem);

    const int t    = threadIdx.x;
    const int wid  = t >> 5, lane = t & 31;
    const int m0   = blockIdx.x * M_TILE;
    const size_t kb0 = (size_t)blockIdx.y * KCHUNK;

    const int wr = wid >> 1;
    const int wn = wid & 1;

    const int arow0 = t >> 4;
    const int apos  = t & 15;
    const float* Asrc = A + (size_t)m0 * KFULL + kb0 + apos * 4;

    const int bn = t >> 3, bkc = t & 7;
    const uint32_t boff = bn * 128 + ((bkc ^ (bn & 7)) << 4);
    const __half* bsrc_h = g_Bh + (size_t)bn * KFULL + kb0 + bkc * 8;
    const __half* bsrc_l = g_Bl + (size_t)bn * KFULL + kb0 + bkc * 8;

    const int a_row  = wr * 32 + (lane & 15);
    const int a_csel = lane >> 4;
    const int bg     = lane >> 3;
    const int b_nrow = wn * 16 + ((bg >> 1) << 3) + (lane & 7);
    const int b_csel = bg & 1;

    cp_async16(sbase + OFF_B + 0 * B_STG + boff, bsrc_h);
    cp_async16(sbase + OFF_B + 0 * B_STG + 4096 + boff, bsrc_l);
    asm volatile("cp.async.commit_group;");
    cp_async16(sbase + OFF_B + 1 * B_STG + boff, bsrc_h + KT);
    cp_async16(sbase + OFF_B + 1 * B_STG + 4096 + boff, bsrc_l + KT);
    asm volatile("cp.async.commit_group;");

    float4 areg[8];
#pragma unroll
    for (int i = 0; i < 8; ++i)
        areg[i] = ldcs4(Asrc + (size_t)(arow0 + 16 * i) * KFULL);

    float d[2][2][4] = {};

    for (int step = 0; step < NSTEPS; ++step) {
        const int abuf = step & 1;
        const uint32_t asm_base = sbase + abuf * 16384;

        {
            const int chunk = apos >> 1, half = apos & 1;
#pragma unroll
            for (int i = 0; i < 8; ++i) {
                const int row = arow0 + 16 * i;
                float4 f = areg[i];
                uint32_t h01, h23;
                asm("cvt.rn.f16x2.f32 %0, %1, %2;" : "=r"(h01) : "f"(f.y), "f"(f.x));
                asm("cvt.rn.f16x2.f32 %0, %1, %2;" : "=r"(h23) : "f"(f.w), "f"(f.z));
                const uint32_t off = row * 128 + ((chunk ^ (row & 7)) << 4) + half * 8;
                *(uint2*)(smem + abuf * 16384 + off) = make_uint2(h01, h23);
            }
        }

        if (step + 1 < NSTEPS) {
            const float* asrc2 = Asrc + (step + 1) * KT;
#pragma unroll
            for (int i = 0; i < 8; ++i)
                areg[i] = ldcs4(asrc2 + (size_t)(arow0 + 16 * i) * KFULL);
        }
        if (step + 2 < NSTEPS) {
            const uint32_t bslot = sbase + OFF_B + ((step + 2) & 3) * B_STG;
            cp_async16(bslot + boff, bsrc_h + (step + 2) * KT);
            cp_async16(bslot + 4096 + boff, bsrc_l + (step + 2) * KT);
        }
        asm volatile("cp.async.commit_group;");
        asm volatile("cp.async.wait_group 2;");
        __syncthreads();

        const uint32_t a_base0 = asm_base + a_row * 128;
        const uint32_t a_base1 = a_base0 + 16 * 128;
        const uint32_t bstg    = sbase + OFF_B + (step & 3) * B_STG + b_nrow * 128;
#pragma unroll
        for (int kt = 0; kt < 4; ++kt) {
            const int achunk = (2 * kt + a_csel) ^ (lane & 7);
            const int bchunk = (2 * kt + b_csel) ^ (lane & 7);
            uint32_t a0[4], a1[4], bh4[4], bl4[4];
            ldmatrix_x4(a0, a_base0 + (achunk << 4));
            ldmatrix_x4(a1, a_base1 + (achunk << 4));
            ldmatrix_x4(bh4, bstg + (bchunk << 4));
            ldmatrix_x4(bl4, bstg + 4096 + (bchunk << 4));
            mma16816(d[0][0], a0, bh4[0], bh4[1]);
            mma16816(d[0][0], a0, bl4[0], bl4[1]);
            mma16816(d[0][1], a0, bh4[2], bh4[3]);
            mma16816(d[0][1], a0, bl4[2], bl4[3]);
            mma16816(d[1][0], a1, bh4[0], bh4[1]);
            mma16816(d[1][0], a1, bl4[0], bl4[1]);
            mma16816(d[1][1], a1, bh4[2], bh4[3]);
            mma16816(d[1][1], a1, bl4[2], bl4[3]);
        }
    }

    // epilogue: fp16 partials
    const int r4 = lane >> 2, kq = (lane & 3) * 2;
    __half* po = g_part + ((size_t)blockIdx.y * NNODES + m0 + wr * 32 + r4) * DOUT
                        + wn * 16 + kq;
#pragma unroll
    for (int rt = 0; rt < 2; ++rt)
#pragma unroll
        for (int nn = 0; nn < 2; ++nn) {
            *(__half2*)(po + (size_t)(rt * 16)     * DOUT + nn * 8) =
                __floats2half2_rn(d[rt][nn][0], d[rt][nn][1]);
            *(__half2*)(po + (size_t)(rt * 16 + 8) * DOUT + nn * 8) =
                __floats2half2_rn(d[rt][nn][2], d[rt][nn][3]);
        }
}

// Stage 4: deterministic split-K reduction (half2 grain, 4 split streams for MLP)
__global__ void k_reduce(float* __restrict__ out) {
    int i = blockIdx.x * blockDim.x + threadIdx.x;   // over 65536 half2s
    const __half2* p = (const __half2*)g_part;
    const size_t stride = (size_t)(NNODES * DOUT / 2);
    float2 s0 = {0.f, 0.f}, s1 = {0.f, 0.f}, s2 = {0.f, 0.f}, s3 = {0.f, 0.f};
#pragma unroll
    for (int sdx = 0; sdx < KSPLIT; sdx += 4) {
        float2 v0 = __half22float2(p[(size_t)(sdx + 0) * stride + i]);
        float2 v1 = __half22float2(p[(size_t)(sdx + 1) * stride + i]);
        float2 v2 = __half22float2(p[(size_t)(sdx + 2) * stride + i]);
        float2 v3 = __half22float2(p[(size_t)(sdx + 3) * stride + i]);
        s0.x += v0.x; s0.y += v0.y; s1.x += v1.x; s1.y += v1.y;
        s2.x += v2.x; s2.y += v2.y; s3.x += v3.x; s3.y += v3.y;
    }
    float2 s = make_float2(s0.x + s1.x + s2.x + s3.x,
                           s0.y + s1.y + s2.y + s3.y);
    ((float2*)out)[i] = s;
}

extern "C" void kernel_launch(void* const* d_in, const int* in_sizes, int n_in,
                              void* d_out, int out_size) {
    const float* X    = (const float*)d_in[0];   // [4096, 64]
    const float* A    = (const float*)d_in[1];   // [4096, 65536]
    const float* WF   = (const float*)d_in[2];   // [8, 64, 32]
    const float* comp = (const float*)d_in[3];   // [16, 8]
    float* out = (float*)d_out;                  // [4096, 32]

    cudaFuncSetAttribute((const void*)k_gemm,
                         cudaFuncAttributeMaxDynamicSharedMemorySize, SMEM_BYTES);

    k_fw<<<dim3(RREL, NNODES / FW_ROWS), 256>>>(X, WF, comp);
    k_gemm<<<dim3(NNODES / M_TILE, KSPLIT), 256, SMEM_BYTES>>>(A);
    k_reduce<<<(NNODES * DOUT / 2) / 256, 256>>>(out);
}

// round 17
// speedup vs baseline: 1.0761x; 1.0300x over previous
#include <cuda_runtime.h>
#include <cuda_fp16.h>
#include <cstdint>

#define NNODES 4096
#define RREL   16
#define NBASES 8
#define DIN    64
#define DOUT   32
#define KFULL  (RREL * NNODES)          // 65536

#define M_TILE 128
#define KT     64                       // k per step (4 mma k-tiles of 16)
#define KSPLIT 64
#define KCHUNK (KFULL / KSPLIT)         // 1024
#define NSTEPS (KCHUNK / KT)            // 16

// gemm smem: A f16 tiles 2 x 16KB | B 4-slot ring, each slot BH 4K + BL 4K
#define OFF_B  32768
#define B_STG  8192
#define SMEM_BYTES (32768 + 4 * B_STG)  // 64 KB dynamic

// k_fw smem layout (dynamic, 48 KB)
#define FW_WS   0                       // 8 KB fp32 W_r
#define FW_XH   8192                    // 16 KB X hi tile (swizzled)
#define FW_XL   24576                   // 16 KB X lo tile
#define FW_WTH  40960                   // 4 KB W^T hi (swizzled)
#define FW_WTL  45056                   // 4 KB W^T lo
#define FW_SMEM 49152
#define FW_SH   8192                    // staging hi overlays XH (dead)
#define FW_SL   16896                   // staging lo
#define SP2     136                     // staging pitch (halves, 16B-mult)

__device__ __half g_Bh[(size_t)DOUT * KFULL];            // [c][k], 4 MB
__device__ __half g_Bl[(size_t)DOUT * KFULL];            // 4 MB
__device__ __half g_part[(size_t)KSPLIT * NNODES * DOUT]; // fp16 partials, 16 MB

__device__ __forceinline__ void mma16816(float* d, const uint32_t* a,
                                         uint32_t b0, uint32_t b1) {
    asm volatile(
        "mma.sync.aligned.m16n8k16.row.col.f32.f16.f16.f32 "
        "{%0,%1,%2,%3}, {%4,%5,%6,%7}, {%8,%9}, {%0,%1,%2,%3};"
        : "+f"(d[0]), "+f"(d[1]), "+f"(d[2]), "+f"(d[3])
        : "r"(a[0]), "r"(a[1]), "r"(a[2]), "r"(a[3]), "r"(b0), "r"(b1));
}
__device__ __forceinline__ void cp_async16(uint32_t saddr, const void* g) {
    asm volatile("cp.async.cg.shared.global [%0], [%1], 16;" :: "r"(saddr), "l"(g));
}
__device__ __forceinline__ void ldmatrix_x4(uint32_t* r, uint32_t addr) {
    asm volatile("ldmatrix.sync.aligned.m8n8.x4.shared.b16 {%0,%1,%2,%3}, [%4];"
                 : "=r"(r[0]), "=r"(r[1]), "=r"(r[2]), "=r"(r[3]) : "r"(addr));
}
// evict-first streaming load (A is single-use; keep B hot in L2)
__device__ __forceinline__ float4 ldcs4(const float* p) {
    float4 v;
    asm volatile("ld.global.cs.v4.f32 {%0,%1,%2,%3}, [%4];"
                 : "=f"(v.x), "=f"(v.y), "=f"(v.z), "=f"(v.w) : "l"(p));
    return v;
}

// Stage 1+2 on tensor cores: W_r = comp[r].WF; FW-tile = X-tile @ W_r via
// 3-product fp16 hi/lo mma; FW split hi/lo, transposed [c][k], coalesced store.
__global__ __launch_bounds__(256) void k_fw(const float* __restrict__ X,
                                            const float* __restrict__ WF,
                                            const float* __restrict__ comp) {
    extern __shared__ char fsm[];
    float* Ws = (float*)(fsm + FW_WS);
    const int r = blockIdx.x, mt = blockIdx.y, t = threadIdx.x;
    const int wid = t >> 5, lane = t & 31;
    const int wr = wid >> 1, wn = wid & 1;

    // W_r: 2048 fp32 entries, 8 per thread
#pragma unroll
    for (int j = 0; j < 8; ++j) {
        int ij = t + 256 * j;
        float s = 0.f;
#pragma unroll
        for (int b = 0; b < NBASES; ++b)
            s += comp[r * NBASES + b] * WF[b * (DIN * DOUT) + ij];
        Ws[ij] = s;
    }

    // X tile 128x64: load fp32, split fp16 hi/lo, swizzled STS
    {
        const int arow0 = t >> 4, apos = t & 15;
        const int chunk = apos >> 1, half = apos & 1;
#pragma unroll
        for (int i = 0; i < 8; ++i) {
            const int row = arow0 + 16 * i;
            float4 f = *(const float4*)&X[(size_t)(mt * M_TILE + row) * DIN + apos * 4];
            uint32_t h01, h23, l01, l23;
            asm("cvt.rn.f16x2.f32 %0, %1, %2;" : "=r"(h01) : "f"(f.y), "f"(f.x));
            asm("cvt.rn.f16x2.f32 %0, %1, %2;" : "=r"(h23) : "f"(f.w), "f"(f.z));
            float2 hf01 = __half22float2(*(__half2*)&h01);
            float2 hf23 = __half22float2(*(__half2*)&h23);
            asm("cvt.rn.f16x2.f32 %0, %1, %2;" : "=r"(l01)
                : "f"(f.y - hf01.y), "f"(f.x - hf01.x));
            asm("cvt.rn.f16x2.f32 %0, %1, %2;" : "=r"(l23)
                : "f"(f.w - hf23.y), "f"(f.z - hf23.x));
            const uint32_t off = row * 128 + ((chunk ^ (row & 7)) << 4) + half * 8;
            *(uint2*)(fsm + FW_XH + off) = make_uint2(h01, h23);
            *(uint2*)(fsm + FW_XL + off) = make_uint2(l01, l23);
        }
    }
    __syncthreads();

    // W^T tiles 32x64 (swizzled), hi/lo: entry W[k][n] -> row n, k-pos
#pragma unroll
    for (int j = 0; j < 8; ++j) {
        int ij = t + 256 * j;
        int k = ij >> 5, n = ij & 31;
        float v = Ws[ij];
        __half h = __float2half_rn(v);
        __half l = __float2half_rn(v - __half2float(h));
        uint32_t off = n * 128 + (((k >> 3) ^ (n & 7)) << 4) + (k & 7) * 2;
        *(__half*)(fsm + FW_WTH + off) = h;
        *(__half*)(fsm + FW_WTL + off) = l;
    }
    __syncthreads();

    // mma: D = Xh.Wh + Xh.Wl + Xl.Wh (identical fragment patterns to k_gemm)
    const int a_row  = wr * 32 + (lane & 15);
    const int a_csel = lane >> 4;
    const int bg     = lane >> 3;
    const int b_nrow = wn * 16 + ((bg >> 1) << 3) + (lane & 7);
    const int b_csel = bg & 1;
    const uint32_t sb = (uint32_t)__cvta_generic_to_shared(fsm);
    const uint32_t axh = sb + FW_XH + a_row * 128;
    const uint32_t axl = sb + FW_XL + a_row * 128;
    const uint32_t bwh = sb + FW_WTH + b_nrow * 128;
    const uint32_t bwl = sb + FW_WTL + b_nrow * 128;

    float d[2][2][4] = {};
#pragma unroll
    for (int kt = 0; kt < 4; ++kt) {
        const int achunk = (2 * kt + a_csel) ^ (lane & 7);
        const int bchunk = (2 * kt + b_csel) ^ (lane & 7);
        uint32_t a0h[4], a1h[4], a0l[4], a1l[4], bh4[4], bl4[4];
        ldmatrix_x4(a0h, axh + (achunk << 4));
        ldmatrix_x4(a1h, axh + 16 * 128 + (achunk << 4));
        ldmatrix_x4(a0l, axl + (achunk << 4));
        ldmatrix_x4(a1l, axl + 16 * 128 + (achunk << 4));
        ldmatrix_x4(bh4, bwh + (bchunk << 4));
        ldmatrix_x4(bl4, bwl + (bchunk << 4));
        mma16816(d[0][0], a0h, bh4[0], bh4[1]);
        mma16816(d[0][0], a0h, bl4[0], bl4[1]);
        mma16816(d[0][0], a0l, bh4[0], bh4[1]);
        mma16816(d[0][1], a0h, bh4[2], bh4[3]);
        mma16816(d[0][1], a0h, bl4[2], bl4[3]);
        mma16816(d[0][1], a0l, bh4[2], bh4[3]);
        mma16816(d[1][0], a1h, bh4[0], bh4[1]);
        mma16816(d[1][0], a1h, bl4[0], bl4[1]);
        mma16816(d[1][0], a1l, bh4[0], bh4[1]);
        mma16816(d[1][1], a1h, bh4[2], bh4[3]);
        mma16816(d[1][1], a1h, bl4[2], bl4[3]);
        mma16816(d[1][1], a1l, bh4[2], bh4[3]);
    }
    __syncthreads();    // X reads done before staging overlays XH/XL

    // stage FW hi/lo transposed [col][row]
    __half* Sh = (__half*)(fsm + FW_SH);
    __half* Sl = (__half*)(fsm + FW_SL);
    const int r4 = lane >> 2, kq = (lane & 3) * 2;
#pragma unroll
    for (int rt = 0; rt < 2; ++rt)
#pragma unroll
        for (int nn = 0; nn < 2; ++nn) {
            const int col = wn * 16 + nn * 8 + kq;
            const int row = wr * 32 + rt * 16 + r4;
#pragma unroll
            for (int jj = 0; jj < 2; ++jj) {
                float v0 = d[rt][nn][jj];       // row
                float v1 = d[rt][nn][2 + jj];   // row + 8
                __half h0 = __float2half_rn(v0);
                __half l0 = __float2half_rn(v0 - __half2float(h0));
                __half h1 = __float2half_rn(v1);
                __half l1 = __float2half_rn(v1 - __half2float(h1));
                Sh[(col + jj) * SP2 + row]     = h0;
                Sh[(col + jj) * SP2 + row + 8] = h1;
                Sl[(col + jj) * SP2 + row]     = l0;
                Sl[(col + jj) * SP2 + row + 8] = l1;
            }
        }
    __syncthreads();

    // coalesced writeout: 32 cols x 16 uint4 chunks (256B contiguous/column)
    const int kbase = r * NNODES + mt * M_TILE;
#pragma unroll
    for (int q = 0; q < 2; ++q) {
        int idx = t + 256 * q;
        int col = idx >> 4, ch = idx & 15;
        uint4 vh = *(const uint4*)&Sh[col * SP2 + ch * 8];
        uint4 vl = *(const uint4*)&Sl[col * SP2 + ch * 8];
        *(uint4*)&g_Bh[(size_t)col * KFULL + kbase + ch * 8] = vh;
        *(uint4*)&g_Bl[(size_t)col * KFULL + kbase + ch * 8] = vl;
    }
}

// Stage 3: split-K GEMM. Streaming LDG.cs -> in-reg fp16 convert -> swizzled
// smem (A 2-buf, B 4-slot cp.async ring) -> ldmatrix x4 -> 2-product mma.
__global__ __launch_bounds__(256, 2) void k_gemm(const float* __restrict__ A) {
    extern __shared__ char smem[];
    const uint32_t sbase = (uint32_t)__cvta_generic_to_shared(smem);

    const int t    = threadIdx.x;
    const int wid  = t >> 5, lane = t & 31;
    const int m0   = blockIdx.x * M_TILE;
    const size_t kb0 = (size_t)blockIdx.y * KCHUNK;

    const int wr = wid >> 1;
    const int wn = wid & 1;

    const int arow0 = t >> 4;
    const int apos  = t & 15;
    const float* Asrc = A + (size_t)m0 * KFULL + kb0 + apos * 4;

    const int bn = t >> 3, bkc = t & 7;
    const uint32_t boff = bn * 128 + ((bkc ^ (bn & 7)) << 4);
    const __half* bsrc_h = g_Bh + (size_t)bn * KFULL + kb0 + bkc * 8;
    const __half* bsrc_l = g_Bl + (size_t)bn * KFULL + kb0 + bkc * 8;

    const int a_row  = wr * 32 + (lane & 15);
    const int a_csel = lane >> 4;
    const int bg     = lane >> 3;
    const int b_nrow = wn * 16 + ((bg >> 1) << 3) + (lane & 7);
    const int b_csel = bg & 1;

    cp_async16(sbase + OFF_B + 0 * B_STG + boff, bsrc_h);
    cp_async16(sbase + OFF_B + 0 * B_STG + 4096 + boff, bsrc_l);
    asm volatile("cp.async.commit_group;");
    cp_async16(sbase + OFF_B + 1 * B_STG + boff, bsrc_h + KT);
    cp_async16(sbase + OFF_B + 1 * B_STG + 4096 + boff, bsrc_l + KT);
    asm volatile("cp.async.commit_group;");

    float4 areg[8];
#pragma unroll
    for (int i = 0; i < 8; ++i)
        areg[i] = ldcs4(Asrc + (size_t)(arow0 + 16 * i) * KFULL);

    float d[2][2][4] = {};

    for (int step = 0; step < NSTEPS; ++step) {
        const int abuf = step & 1;
        const uint32_t asm_base = sbase + abuf * 16384;

        {
            const int chunk = apos >> 1, half = apos & 1;
#pragma unroll
            for (int i = 0; i < 8; ++i) {
                const int row = arow0 + 16 * i;
                float4 f = areg[i];
                uint32_t h01, h23;
                asm("cvt.rn.f16x2.f32 %0, %1, %2;" : "=r"(h01) : "f"(f.y), "f"(f.x));
                asm("cvt.rn.f16x2.f32 %0, %1, %2;" : "=r"(h23) : "f"(f.w), "f"(f.z));
                const uint32_t off = row * 128 + ((chunk ^ (row & 7)) << 4) + half * 8;
                *(uint2*)(smem + abuf * 16384 + off) = make_uint2(h01, h23);
            }
        }

        if (step + 1 < NSTEPS) {
            const float* asrc2 = Asrc + (step + 1) * KT;
#pragma unroll
            for (int i = 0; i < 8; ++i)
                areg[i] = ldcs4(asrc2 + (size_t)(arow0 + 16 * i) * KFULL);
        }
        if (step + 2 < NSTEPS) {
            const uint32_t bslot = sbase + OFF_B + ((step + 2) & 3) * B_STG;
            cp_async16(bslot + boff, bsrc_h + (step + 2) * KT);
            cp_async16(bslot + 4096 + boff, bsrc_l + (step + 2) * KT);
        }
        asm volatile("cp.async.commit_group;");
        asm volatile("cp.async.wait_group 2;");
        __syncthreads();

        const uint32_t a_base0 = asm_base + a_row * 128;
        const uint32_t a_base1 = a_base0 + 16 * 128;
        const uint32_t bstg    = sbase + OFF_B + (step & 3) * B_STG + b_nrow * 128;
#pragma unroll
        for (int kt = 0; kt < 4; ++kt) {
            const int achunk = (2 * kt + a_csel) ^ (lane & 7);
            const int bchunk = (2 * kt + b_csel) ^ (lane & 7);
            uint32_t a0[4], a1[4], bh4[4], bl4[4];
            ldmatrix_x4(a0, a_base0 + (achunk << 4));
            ldmatrix_x4(a1, a_base1 + (achunk << 4));
            ldmatrix_x4(bh4, bstg + (bchunk << 4));
            ldmatrix_x4(bl4, bstg + 4096 + (bchunk << 4));
            mma16816(d[0][0], a0, bh4[0], bh4[1]);
            mma16816(d[0][0], a0, bl4[0], bl4[1]);
            mma16816(d[0][1], a0, bh4[2], bh4[3]);
            mma16816(d[0][1], a0, bl4[2], bl4[3]);
            mma16816(d[1][0], a1, bh4[0], bh4[1]);
            mma16816(d[1][0], a1, bl4[0], bl4[1]);
            mma16816(d[1][1], a1, bh4[2], bh4[3]);
            mma16816(d[1][1], a1, bl4[2], bl4[3]);
        }
    }

    // epilogue: fp16 partials
    const int r4 = lane >> 2, kq = (lane & 3) * 2;
    __half* po = g_part + ((size_t)blockIdx.y * NNODES + m0 + wr * 32 + r4) * DOUT
                        + wn * 16 + kq;
#pragma unroll
    for (int rt = 0; rt < 2; ++rt)
#pragma unroll
        for (int nn = 0; nn < 2; ++nn) {
            *(__half2*)(po + (size_t)(rt * 16)     * DOUT + nn * 8) =
                __floats2half2_rn(d[rt][nn][0], d[rt][nn][1]);
            *(__half2*)(po + (size_t)(rt * 16 + 8) * DOUT + nn * 8) =
                __floats2half2_rn(d[rt][nn][2], d[rt][nn][3]);
        }
}

// Stage 4: deterministic split-K reduction (half2 grain, 4 split streams for MLP)
__global__ void k_reduce(float* __restrict__ out) {
    int i = blockIdx.x * blockDim.x + threadIdx.x;   // over 65536 half2s
    const __half2* p = (const __half2*)g_part;
    const size_t stride = (size_t)(NNODES * DOUT / 2);
    float2 s0 = {0.f, 0.f}, s1 = {0.f, 0.f}, s2 = {0.f, 0.f}, s3 = {0.f, 0.f};
#pragma unroll
    for (int sdx = 0; sdx < KSPLIT; sdx += 4) {
        float2 v0 = __half22float2(p[(size_t)(sdx + 0) * stride + i]);
        float2 v1 = __half22float2(p[(size_t)(sdx + 1) * stride + i]);
        float2 v2 = __half22float2(p[(size_t)(sdx + 2) * stride + i]);
        float2 v3 = __half22float2(p[(size_t)(sdx + 3) * stride + i]);
        s0.x += v0.x; s0.y += v0.y; s1.x += v1.x; s1.y += v1.y;
        s2.x += v2.x; s2.y += v2.y; s3.x += v3.x; s3.y += v3.y;
    }
    float2 s = make_float2(s0.x + s1.x + s2.x + s3.x,
                           s0.y + s1.y + s2.y + s3.y);
    ((float2*)out)[i] = s;
}

extern "C" void kernel_launch(void* const* d_in, const int* in_sizes, int n_in,
                              void* d_out, int out_size) {
    const float* X    = (const float*)d_in[0];   // [4096, 64]
    const float* A    = (const float*)d_in[1];   // [4096, 65536]
    const float* WF   = (const float*)d_in[2];   // [8, 64, 32]
    const float* comp = (const float*)d_in[3];   // [16, 8]
    float* out = (float*)d_out;                  // [4096, 32]

    cudaFuncSetAttribute((const void*)k_gemm,
                         cudaFuncAttributeMaxDynamicSharedMemorySize, SMEM_BYTES);
    cudaFuncSetAttribute((const void*)k_fw,
                         cudaFuncAttributeMaxDynamicSharedMemorySize, FW_SMEM);

    k_fw<<<dim3(RREL, NNODES / M_TILE), 256, FW_SMEM>>>(X, WF, comp);
    k_gemm<<<dim3(NNODES / M_TILE, KSPLIT), 256, SMEM_BYTES>>>(A);
    k_reduce<<<(NNODES * DOUT / 2) / 256, 256>>>(out);
}